// round 5
// baseline (speedup 1.0000x reference)
#include <cuda_runtime.h>
#include <math.h>

#define NN   262144
#define DIMM 256
#define NH   4
#define HD   64
#define BSEG 4096
#define SCALE 0.125f
#define EPSV 1e-8f
#define BT   32     // segments per block in output kernel
#define WPAD 260    // padded vw row: mult of 4 (16B-aligned rows); lane stride 260 ≡ 4 (mod 32)

// ---- device scratch ----
__device__ float g_wtil[NH * DIMM];      // SCALE * (q[h] dot Wk rows)
__device__ float g_ctil[NH];             // SCALE * (q[h] dot key_b slice)
__device__ int   g_segstart[BSEG + 1];
__device__ float g_t[BSEG * NH * DIMM];  // NORMALIZED weighted sums t~ (16 MB)
__device__ float g_coef[BSEG * NH];      // esum/(esum+eps) per segment/head

// ---- packed f32x2 helpers ----
__device__ __forceinline__ unsigned long long f2mul(unsigned long long a, unsigned long long b) {
    unsigned long long r; asm("mul.rn.f32x2 %0,%1,%2;" : "=l"(r) : "l"(a), "l"(b)); return r;
}
__device__ __forceinline__ unsigned long long f2fma(unsigned long long a, unsigned long long b,
                                                    unsigned long long c) {
    unsigned long long r; asm("fma.rn.f32x2 %0,%1,%2,%3;" : "=l"(r) : "l"(a), "l"(b), "l"(c)); return r;
}
__device__ __forceinline__ unsigned long long fpack(float a, float b) {
    unsigned long long r; asm("mov.b64 %0,{%1,%2};" : "=l"(r) : "f"(a), "f"(b)); return r;
}
__device__ __forceinline__ float f2lo(unsigned long long a) { float2 p = *(float2*)&a; return p.x; }
__device__ __forceinline__ float f2hi(unsigned long long a) { float2 p = *(float2*)&a; return p.y; }

// ---------------------------------------------------------------------------
// Kernel 1: fold query into key weights.
// ---------------------------------------------------------------------------
__global__ void k_fold(const float* __restrict__ q,
                       const float* __restrict__ kw,
                       const float* __restrict__ kb) {
    int h = blockIdx.x;
    int j = threadIdx.x;
    float acc = 0.f;
#pragma unroll 8
    for (int d = 0; d < HD; d++)
        acc = fmaf(q[h * HD + d], kw[(h * HD + d) * DIMM + j], acc);
    g_wtil[h * DIMM + j] = acc * SCALE;
    if (j == 0) {
        float c = 0.f;
#pragma unroll 8
        for (int d = 0; d < HD; d++)
            c = fmaf(q[h * HD + d], kb[h * HD + d], c);
        g_ctil[h] = c * SCALE;
    }
}

// ---------------------------------------------------------------------------
// Kernel 2: segment boundaries by linear adjacent-diff scan (batch sorted).
// ---------------------------------------------------------------------------
__global__ void k_seg(const int* __restrict__ batch) {
    int i = blockIdx.x * blockDim.x + threadIdx.x;
    if (i >= NN) return;
    int cur  = batch[i];
    int prev = (i == 0) ? -1 : batch[i - 1];
    for (int b = prev + 1; b <= cur; b++) g_segstart[b] = i;
    if (i == NN - 1)
        for (int b = cur + 1; b <= BSEG; b++) g_segstart[b] = NN;
}

// ---------------------------------------------------------------------------
// Kernel 3: warp per segment, fully register-resident. x read once HBM->regs.
// Per row: dot(4 heads, f32x2) -> shuffle reduce -> exp -> broadcast ->
// register accumulate. Epilogue folds 1/(esum+eps) into t~ and emits coef.
// No shared memory, no __syncthreads.
// ---------------------------------------------------------------------------
__global__ void __launch_bounds__(128) k_main(const float* __restrict__ x) {
    const int lane = threadIdx.x & 31;
    const int b    = blockIdx.x * 4 + (threadIdx.x >> 5);

    const int s0 = g_segstart[b];
    const int s1 = g_segstart[b + 1];

    // folded weights for this lane's j's (j = lane*4..+3 and 128+lane*4..+3)
    const float4* wt4 = (const float4*)g_wtil;
    ulonglong2 w0[NH], w1[NH];
#pragma unroll
    for (int h = 0; h < NH; h++) {
        float4 t = wt4[h * 64 + lane];      w0[h] = *(ulonglong2*)&t;
        float4 u = wt4[h * 64 + 32 + lane]; w1[h] = *(ulonglong2*)&u;
    }
    const float ct0 = g_ctil[0], ct1 = g_ctil[1], ct2 = g_ctil[2], ct3 = g_ctil[3];
    const float ctv = (lane < 8) ? ct0 : (lane < 16) ? ct1 : (lane < 24) ? ct2 : ct3;

    ulonglong2 accA[NH], accB[NH];
#pragma unroll
    for (int h = 0; h < NH; h++) { accA[h].x = accA[h].y = 0ull; accB[h].x = accB[h].y = 0ull; }
    float es0 = 0.f, es1 = 0.f, es2 = 0.f, es3 = 0.f;

    const float4* xp = (const float4*)x;
    float4 c0 = make_float4(0.f,0.f,0.f,0.f), c1 = c0, n0 = c0, n1 = c0;
    if (s0 < s1) {
        c0 = xp[(size_t)s0 * 64 + lane];
        c1 = xp[(size_t)s0 * 64 + 32 + lane];
    }

    for (int r = s0; r < s1; r++) {
        const bool more = (r + 1 < s1);
        if (more) {   // prefetch next row while computing current
            n0 = xp[(size_t)(r + 1) * 64 + lane];
            n1 = xp[(size_t)(r + 1) * 64 + 32 + lane];
        }
        ulonglong2 v0 = *(ulonglong2*)&c0;
        ulonglong2 v1 = *(ulonglong2*)&c1;

        // per-head partial dots (f32x2)
        float a0, a1, a2, a3;
        {
            unsigned long long p;
            p = f2mul(v0.x, w0[0].x); p = f2fma(v0.y, w0[0].y, p);
            p = f2fma(v1.x, w1[0].x, p); p = f2fma(v1.y, w1[0].y, p);
            a0 = f2lo(p) + f2hi(p);
            p = f2mul(v0.x, w0[1].x); p = f2fma(v0.y, w0[1].y, p);
            p = f2fma(v1.x, w1[1].x, p); p = f2fma(v1.y, w1[1].y, p);
            a1 = f2lo(p) + f2hi(p);
            p = f2mul(v0.x, w0[2].x); p = f2fma(v0.y, w0[2].y, p);
            p = f2fma(v1.x, w1[2].x, p); p = f2fma(v1.y, w1[2].y, p);
            a2 = f2lo(p) + f2hi(p);
            p = f2mul(v0.x, w0[3].x); p = f2fma(v0.y, w0[3].y, p);
            p = f2fma(v1.x, w1[3].x, p); p = f2fma(v1.y, w1[3].y, p);
            a3 = f2lo(p) + f2hi(p);
        }
        // fold 16, 8 on all heads
#pragma unroll
        for (int o = 16; o >= 8; o >>= 1) {
            a0 += __shfl_xor_sync(0xffffffffu, a0, o);
            a1 += __shfl_xor_sync(0xffffffffu, a1, o);
            a2 += __shfl_xor_sync(0xffffffffu, a2, o);
            a3 += __shfl_xor_sync(0xffffffffu, a3, o);
        }
        // lane group -> head; finish butterfly within group of 8
        float val = (lane < 8) ? a0 : (lane < 16) ? a1 : (lane < 24) ? a2 : a3;
        val += __shfl_xor_sync(0xffffffffu, val, 4);
        val += __shfl_xor_sync(0xffffffffu, val, 2);
        val += __shfl_xor_sync(0xffffffffu, val, 1);
        float e = __expf(val + ctv);
        float e0 = __shfl_sync(0xffffffffu, e, 0);
        float e1 = __shfl_sync(0xffffffffu, e, 8);
        float e2 = __shfl_sync(0xffffffffu, e, 16);
        float e3 = __shfl_sync(0xffffffffu, e, 24);
        es0 += e0; es1 += e1; es2 += e2; es3 += e3;

        unsigned long long ee0 = fpack(e0, e0), ee1 = fpack(e1, e1);
        unsigned long long ee2 = fpack(e2, e2), ee3 = fpack(e3, e3);
        accA[0].x = f2fma(ee0, v0.x, accA[0].x); accA[0].y = f2fma(ee0, v0.y, accA[0].y);
        accB[0].x = f2fma(ee0, v1.x, accB[0].x); accB[0].y = f2fma(ee0, v1.y, accB[0].y);
        accA[1].x = f2fma(ee1, v0.x, accA[1].x); accA[1].y = f2fma(ee1, v0.y, accA[1].y);
        accB[1].x = f2fma(ee1, v1.x, accB[1].x); accB[1].y = f2fma(ee1, v1.y, accB[1].y);
        accA[2].x = f2fma(ee2, v0.x, accA[2].x); accA[2].y = f2fma(ee2, v0.y, accA[2].y);
        accB[2].x = f2fma(ee2, v1.x, accB[2].x); accB[2].y = f2fma(ee2, v1.y, accB[2].y);
        accA[3].x = f2fma(ee3, v0.x, accA[3].x); accA[3].y = f2fma(ee3, v0.y, accA[3].y);
        accB[3].x = f2fma(ee3, v1.x, accB[3].x); accB[3].y = f2fma(ee3, v1.y, accB[3].y);

        if (more) { c0 = n0; c1 = n1; }
    }

    // normalize (fold 1/(esum+eps)) and store t~, coef
    float iv0 = 1.0f / (es0 + EPSV), iv1 = 1.0f / (es1 + EPSV);
    float iv2 = 1.0f / (es2 + EPSV), iv3 = 1.0f / (es3 + EPSV);
    unsigned long long ii[NH] = { fpack(iv0, iv0), fpack(iv1, iv1),
                                  fpack(iv2, iv2), fpack(iv3, iv3) };
    float4* tp = (float4*)(g_t + (size_t)b * NH * DIMM);
#pragma unroll
    for (int h = 0; h < NH; h++) {
        ulonglong2 sa, sb;
        sa.x = f2mul(ii[h], accA[h].x); sa.y = f2mul(ii[h], accA[h].y);
        sb.x = f2mul(ii[h], accB[h].x); sb.y = f2mul(ii[h], accB[h].y);
        tp[h * 64 + lane]      = *(float4*)&sa;
        tp[h * 64 + 32 + lane] = *(float4*)&sb;
    }
    if (lane < NH) {
        float cf = (lane == 0) ? es0 * iv0 : (lane == 1) ? es1 * iv1
                 : (lane == 2) ? es2 * iv2 : es3 * iv3;
        g_coef[b * NH + lane] = cf;
    }
}

// ---------------------------------------------------------------------------
// Kernel 4: out[b, h*64+d] = coef[b,h]*bv[h*64+d] + sum_j vw[h*64+d, j]*t~[b,h,j]
// Register tile: thread owns d rows {lane, lane+32} x 4 b's. f32x2 FMAs.
// Row base lane*WPAD: WPAD=260 -> 16B-aligned, lane stride ≡ 4 mod 32 ->
// conflict-free LDS.128 for both row pointers.
// grid = (BSEG/BT, NH), 256 threads.
// ---------------------------------------------------------------------------
__global__ void __launch_bounds__(256) k_out(const float* __restrict__ vw,
                                             const float* __restrict__ vb,
                                             float* __restrict__ out) {
    extern __shared__ float sm[];
    float*      sw     = sm;                            // 64 x WPAD
    ulonglong2* t4     = (ulonglong2*)(sm + 64 * WPAD); // BT x 64 (float4 view)
    float*      coef_s = sm + 64 * WPAD + BT * 64 * 4;

    const int h   = blockIdx.y;
    const int b0  = blockIdx.x * BT;
    const int tid = threadIdx.x;

    {
        const float4* vw4 = (const float4*)(vw + (size_t)h * 64 * DIMM);
        for (int i = tid; i < 64 * 64; i += 256) {
            int d = i >> 6, c = i & 63;
            *(float4*)(sw + d * WPAD + c * 4) = vw4[i];
        }
    }
    for (int i = tid; i < BT * 64; i += 256) {
        int row = i >> 6, c = i & 63;
        t4[row * 64 + c] = ((const ulonglong2*)g_t)[((size_t)(b0 + row) * NH + h) * 64 + c];
    }
    if (tid < BT) coef_s[tid] = g_coef[(b0 + tid) * NH + h];
    __syncthreads();

    const int lane = tid & 31;
    const int wq   = tid >> 5;        // b = b0 + wq + 8k, k = 0..3
    const int d0   = lane;            // rows d0 and d0+32
    const int d1   = lane + 32;

    const ulonglong2* wr0 = (const ulonglong2*)(sw + d0 * WPAD);
    const ulonglong2* wr1 = (const ulonglong2*)(sw + d1 * WPAD);

    unsigned long long acc0[4] = {0ull,0ull,0ull,0ull};
    unsigned long long acc1[4] = {0ull,0ull,0ull,0ull};

#pragma unroll 8
    for (int j4 = 0; j4 < 64; j4++) {
        ulonglong2 wa = wr0[j4];   // LDS.128, conflict-free
        ulonglong2 wb = wr1[j4];
#pragma unroll
        for (int k = 0; k < 4; k++) {
            ulonglong2 s = t4[(wq + 8 * k) * 64 + j4];   // broadcast across lanes
            acc0[k] = f2fma(wa.x, s.x, acc0[k]);
            acc0[k] = f2fma(wa.y, s.y, acc0[k]);
            acc1[k] = f2fma(wb.x, s.x, acc1[k]);
            acc1[k] = f2fma(wb.y, s.y, acc1[k]);
        }
    }

    const float bva = vb[h * 64 + d0];
    const float bvb = vb[h * 64 + d1];
#pragma unroll
    for (int k = 0; k < 4; k++) {
        int   bb = wq + 8 * k;
        float cf = coef_s[bb];
        float* op = out + (size_t)(b0 + bb) * DIMM + h * 64;
        op[d0] = fmaf(cf, bva, f2lo(acc0[k]) + f2hi(acc0[k]));
        op[d1] = fmaf(cf, bvb, f2lo(acc1[k]) + f2hi(acc1[k]));
    }
}

// ---------------------------------------------------------------------------
extern "C" void kernel_launch(void* const* d_in, const int* in_sizes, int n_in,
                              void* d_out, int out_size) {
    const float* x     = (const float*)d_in[0];
    const int*   batch = (const int*)d_in[1];
    const float* q     = (const float*)d_in[2];
    const float* kw    = (const float*)d_in[3];
    const float* kb    = (const float*)d_in[4];
    const float* vw    = (const float*)d_in[5];
    const float* vb    = (const float*)d_in[6];
    float*       out   = (float*)d_out;

    const int smem_out = 64 * WPAD * 4 + BT * 64 * 16 + BT * 4;   // 99456
    cudaFuncSetAttribute(k_out, cudaFuncAttributeMaxDynamicSharedMemorySize, smem_out);

    k_fold<<<NH, 256>>>(q, kw, kb);
    k_seg<<<NN / 256, 256>>>(batch);
    k_main<<<BSEG / 4, 128>>>(x);
    k_out<<<dim3(BSEG / BT, NH), 256, smem_out>>>(vw, vb, out);
}

// round 6
// speedup vs baseline: 1.3140x; 1.3140x over previous
#include <cuda_runtime.h>
#include <math.h>

#define NN   262144
#define DIMM 256
#define NH   4
#define HD   64
#define BSEG 4096
#define SCALE 0.125f
#define EPSV 1e-8f
#define BT   32     // b-tile per block in output kernel

// ---- device scratch ----
__device__ float g_wtil[NH * DIMM];      // SCALE * (q[h] dot Wk rows)
__device__ float g_ctil[NH];             // SCALE * (q[h] dot key_b slice)
__device__ int   g_segstart[BSEG + 1];
__device__ float g_t[BSEG * NH * DIMM];  // normalized weighted sums t~ (16 MB)
__device__ float g_coef[BSEG * NH];      // esum/(esum+eps)

// ---- packed f32x2 helpers ----
__device__ __forceinline__ unsigned long long f2mul(unsigned long long a, unsigned long long b) {
    unsigned long long r; asm("mul.rn.f32x2 %0,%1,%2;" : "=l"(r) : "l"(a), "l"(b)); return r;
}
__device__ __forceinline__ unsigned long long f2fma(unsigned long long a, unsigned long long b,
                                                    unsigned long long c) {
    unsigned long long r; asm("fma.rn.f32x2 %0,%1,%2,%3;" : "=l"(r) : "l"(a), "l"(b), "l"(c)); return r;
}
__device__ __forceinline__ unsigned long long fpack(float a, float b) {
    unsigned long long r; asm("mov.b64 %0,{%1,%2};" : "=l"(r) : "f"(a), "f"(b)); return r;
}
__device__ __forceinline__ float f2lo(unsigned long long a) { float2 p = *(float2*)&a; return p.x; }
__device__ __forceinline__ float f2hi(unsigned long long a) { float2 p = *(float2*)&a; return p.y; }

// ---------------------------------------------------------------------------
__global__ void k_fold(const float* __restrict__ q,
                       const float* __restrict__ kw,
                       const float* __restrict__ kb) {
    int h = blockIdx.x;
    int j = threadIdx.x;
    float acc = 0.f;
#pragma unroll 8
    for (int d = 0; d < HD; d++)
        acc = fmaf(q[h * HD + d], kw[(h * HD + d) * DIMM + j], acc);
    g_wtil[h * DIMM + j] = acc * SCALE;
    if (j == 0) {
        float c = 0.f;
#pragma unroll 8
        for (int d = 0; d < HD; d++)
            c = fmaf(q[h * HD + d], kb[h * HD + d], c);
        g_ctil[h] = c * SCALE;
    }
}

// ---------------------------------------------------------------------------
__global__ void k_seg(const int* __restrict__ batch) {
    int i = blockIdx.x * blockDim.x + threadIdx.x;
    if (i >= NN) return;
    int cur  = batch[i];
    int prev = (i == 0) ? -1 : batch[i - 1];
    for (int b = prev + 1; b <= cur; b++) g_segstart[b] = i;
    if (i == NN - 1)
        for (int b = cur + 1; b <= BSEG; b++) g_segstart[b] = NN;
}

// ---------------------------------------------------------------------------
// k_main: warp per segment, 2 rows per iteration, 2-slot register ring
// (4 rows = 1KB per warp in flight). 8-item butterfly multi-reduce:
// item = r_local*4 + h lives at lanes 4*item..4*item+3 after the tree.
// ---------------------------------------------------------------------------
__device__ __forceinline__ void process_pair(
    ulonglong2 v0, ulonglong2 v1, ulonglong2 u0, ulonglong2 u1,
    bool row1ok, int lane, float ctv,
    const ulonglong2 (&w0)[NH], const ulonglong2 (&w1)[NH],
    ulonglong2 (&accA)[NH], ulonglong2 (&accB)[NH], float& es)
{
    float a[8];
#pragma unroll
    for (int h = 0; h < NH; h++) {
        unsigned long long p;
        p = f2mul(v0.x, w0[h].x); p = f2fma(v0.y, w0[h].y, p);
        p = f2fma(v1.x, w1[h].x, p); p = f2fma(v1.y, w1[h].y, p);
        a[h] = f2lo(p) + f2hi(p);
        p = f2mul(u0.x, w0[h].x); p = f2fma(u0.y, w0[h].y, p);
        p = f2fma(u1.x, w1[h].x, p); p = f2fma(u1.y, w1[h].y, p);
        a[4 + h] = f2lo(p) + f2hi(p);
    }
    // butterfly multi-reduce: 8 items -> lane (lane>>2)&7 holds its item's sum
    const bool b4 = (lane & 16) != 0;
#pragma unroll
    for (int i = 0; i < 4; i++) {
        float mine = b4 ? a[i + 4] : a[i];
        float oth  = b4 ? a[i]     : a[i + 4];
        oth = __shfl_xor_sync(0xffffffffu, oth, 16);
        a[i] = mine + oth;
    }
    const bool b3 = (lane & 8) != 0;
#pragma unroll
    for (int i = 0; i < 2; i++) {
        float mine = b3 ? a[i + 2] : a[i];
        float oth  = b3 ? a[i]     : a[i + 2];
        oth = __shfl_xor_sync(0xffffffffu, oth, 8);
        a[i] = mine + oth;
    }
    const bool b2 = (lane & 4) != 0;
    float mine = b2 ? a[1] : a[0];
    float oth  = b2 ? a[0] : a[1];
    oth = __shfl_xor_sync(0xffffffffu, oth, 4);
    float c = mine + oth;
    c += __shfl_xor_sync(0xffffffffu, c, 2);
    c += __shfl_xor_sync(0xffffffffu, c, 1);

    float e = __expf(c + ctv);            // lane's item: r=(lane>>4)&1, h=(lane>>2)&3
    if (lane >= 16 && !row1ok) e = 0.f;   // zero padded row
    if ((lane & 3) == 0) es += e;         // one accumulator lane per item

    float e00 = __shfl_sync(0xffffffffu, e, 0);
    float e01 = __shfl_sync(0xffffffffu, e, 4);
    float e02 = __shfl_sync(0xffffffffu, e, 8);
    float e03 = __shfl_sync(0xffffffffu, e, 12);
    float e10 = __shfl_sync(0xffffffffu, e, 16);
    float e11 = __shfl_sync(0xffffffffu, e, 20);
    float e12 = __shfl_sync(0xffffffffu, e, 24);
    float e13 = __shfl_sync(0xffffffffu, e, 28);

    unsigned long long k0 = fpack(e00, e00), k1 = fpack(e01, e01);
    unsigned long long k2 = fpack(e02, e02), k3 = fpack(e03, e03);
    unsigned long long m0 = fpack(e10, e10), m1 = fpack(e11, e11);
    unsigned long long m2 = fpack(e12, e12), m3 = fpack(e13, e13);

    accA[0].x = f2fma(k0, v0.x, accA[0].x); accA[0].y = f2fma(k0, v0.y, accA[0].y);
    accB[0].x = f2fma(k0, v1.x, accB[0].x); accB[0].y = f2fma(k0, v1.y, accB[0].y);
    accA[1].x = f2fma(k1, v0.x, accA[1].x); accA[1].y = f2fma(k1, v0.y, accA[1].y);
    accB[1].x = f2fma(k1, v1.x, accB[1].x); accB[1].y = f2fma(k1, v1.y, accB[1].y);
    accA[2].x = f2fma(k2, v0.x, accA[2].x); accA[2].y = f2fma(k2, v0.y, accA[2].y);
    accB[2].x = f2fma(k2, v1.x, accB[2].x); accB[2].y = f2fma(k2, v1.y, accB[2].y);
    accA[3].x = f2fma(k3, v0.x, accA[3].x); accA[3].y = f2fma(k3, v0.y, accA[3].y);
    accB[3].x = f2fma(k3, v1.x, accB[3].x); accB[3].y = f2fma(k3, v1.y, accB[3].y);

    accA[0].x = f2fma(m0, u0.x, accA[0].x); accA[0].y = f2fma(m0, u0.y, accA[0].y);
    accB[0].x = f2fma(m0, u1.x, accB[0].x); accB[0].y = f2fma(m0, u1.y, accB[0].y);
    accA[1].x = f2fma(m1, u0.x, accA[1].x); accA[1].y = f2fma(m1, u0.y, accA[1].y);
    accB[1].x = f2fma(m1, u1.x, accB[1].x); accB[1].y = f2fma(m1, u1.y, accB[1].y);
    accA[2].x = f2fma(m2, u0.x, accA[2].x); accA[2].y = f2fma(m2, u0.y, accA[2].y);
    accB[2].x = f2fma(m2, u1.x, accB[2].x); accB[2].y = f2fma(m2, u1.y, accB[2].y);
    accA[3].x = f2fma(m3, u0.x, accA[3].x); accA[3].y = f2fma(m3, u0.y, accA[3].y);
    accB[3].x = f2fma(m3, u1.x, accB[3].x); accB[3].y = f2fma(m3, u1.y, accB[3].y);
}

#define LOADS(S, IT) do {                                     \
    int r0_ = s0 + 2 * (IT);                                  \
    int r1_ = (2 * (IT) + 1 < cnt) ? r0_ + 1 : r0_;           \
    S##0 = xp[(size_t)r0_ * 64 + lane];                       \
    S##1 = xp[(size_t)r0_ * 64 + 32 + lane];                  \
    S##2 = xp[(size_t)r1_ * 64 + lane];                       \
    S##3 = xp[(size_t)r1_ * 64 + 32 + lane];                  \
} while (0)

__global__ void __launch_bounds__(128) k_main(const float* __restrict__ x) {
    const int lane = threadIdx.x & 31;
    const int b    = blockIdx.x * 4 + (threadIdx.x >> 5);

    const int s0   = g_segstart[b];
    const int s1   = g_segstart[b + 1];
    const int cnt  = s1 - s0;
    const int niter = (cnt + 1) >> 1;

    const float4* wt4 = (const float4*)g_wtil;
    ulonglong2 w0[NH], w1[NH];
#pragma unroll
    for (int h = 0; h < NH; h++) {
        float4 t = wt4[h * 64 + lane];      w0[h] = *(ulonglong2*)&t;
        float4 u = wt4[h * 64 + 32 + lane]; w1[h] = *(ulonglong2*)&u;
    }
    const float ctv = g_ctil[(lane >> 2) & 3];

    ulonglong2 accA[NH], accB[NH];
#pragma unroll
    for (int h = 0; h < NH; h++) { accA[h].x = accA[h].y = 0ull; accB[h].x = accB[h].y = 0ull; }
    float es = 0.f;

    const float4* xp = (const float4*)x;
    float4 A0, A1, A2, A3, B0, B1, B2, B3;
    if (niter > 0) LOADS(A, 0);
    if (niter > 1) LOADS(B, 1);

    int it = 0;
    for (; it + 1 < niter; it += 2) {
        {
            ulonglong2 v0 = *(ulonglong2*)&A0, v1 = *(ulonglong2*)&A1;
            ulonglong2 u0 = *(ulonglong2*)&A2, u1 = *(ulonglong2*)&A3;
            bool ok = (2 * it + 1) < cnt;
            if (it + 2 < niter) LOADS(A, it + 2);
            process_pair(v0, v1, u0, u1, ok, lane, ctv, w0, w1, accA, accB, es);
        }
        {
            ulonglong2 v0 = *(ulonglong2*)&B0, v1 = *(ulonglong2*)&B1;
            ulonglong2 u0 = *(ulonglong2*)&B2, u1 = *(ulonglong2*)&B3;
            bool ok = (2 * (it + 1) + 1) < cnt;
            if (it + 3 < niter) LOADS(B, it + 3);
            process_pair(v0, v1, u0, u1, ok, lane, ctv, w0, w1, accA, accB, es);
        }
    }
    if (it < niter) {
        ulonglong2 v0 = *(ulonglong2*)&A0, v1 = *(ulonglong2*)&A1;
        ulonglong2 u0 = *(ulonglong2*)&A2, u1 = *(ulonglong2*)&A3;
        bool ok = (2 * it + 1) < cnt;
        process_pair(v0, v1, u0, u1, ok, lane, ctv, w0, w1, accA, accB, es);
    }

    // es: lane 4h (r0) + lane 4h+16 (r1) -> esum[h]
    es += __shfl_xor_sync(0xffffffffu, es, 16);
    float es0 = __shfl_sync(0xffffffffu, es, 0);
    float es1 = __shfl_sync(0xffffffffu, es, 4);
    float es2 = __shfl_sync(0xffffffffu, es, 8);
    float es3 = __shfl_sync(0xffffffffu, es, 12);

    float iv0 = 1.0f / (es0 + EPSV), iv1 = 1.0f / (es1 + EPSV);
    float iv2 = 1.0f / (es2 + EPSV), iv3 = 1.0f / (es3 + EPSV);
    unsigned long long ii[NH] = { fpack(iv0, iv0), fpack(iv1, iv1),
                                  fpack(iv2, iv2), fpack(iv3, iv3) };
    float4* tp = (float4*)(g_t + (size_t)b * NH * DIMM);
#pragma unroll
    for (int h = 0; h < NH; h++) {
        ulonglong2 sa, sb;
        sa.x = f2mul(ii[h], accA[h].x); sa.y = f2mul(ii[h], accA[h].y);
        sb.x = f2mul(ii[h], accB[h].x); sb.y = f2mul(ii[h], accB[h].y);
        tp[h * 64 + lane]      = *(float4*)&sa;
        tp[h * 64 + 32 + lane] = *(float4*)&sb;
    }
    if (lane < NH) {
        float cf = (lane == 0) ? es0 * iv0 : (lane == 1) ? es1 * iv1
                 : (lane == 2) ? es2 * iv2 : es3 * iv3;
        g_coef[b * NH + lane] = cf;
    }
}

// ---------------------------------------------------------------------------
// k_out: 128 threads, 4d x 4b register tile, f32x2. w staged TRANSPOSED in
// smem as [j4][d] (lane stride 16B -> conflict-free LDS.128); t reads are
// broadcasts. 2 B smem / MAC.  grid = (BSEG/BT, NH).
// dyn smem: sw2 64*64 float4 (64KB) | t4 BT*64 float4 (32KB) | coef BT
// ---------------------------------------------------------------------------
__global__ void __launch_bounds__(128) k_out(const float* __restrict__ vw,
                                             const float* __restrict__ vb,
                                             float* __restrict__ out) {
    extern __shared__ float sm[];
    ulonglong2* sw2    = (ulonglong2*)sm;                 // [j4][d]
    ulonglong2* t4     = (ulonglong2*)(sm + 64 * 64 * 4); // [b][j4]
    float*      coef_s = sm + 64 * 64 * 4 + BT * 64 * 4;

    const int h   = blockIdx.y;
    const int b0  = blockIdx.x * BT;
    const int tid = threadIdx.x;

    // stage w transposed: scattered global reads, conflict-free smem writes
    {
        const float4* vw4 = (const float4*)(vw + (size_t)h * 64 * DIMM);
#pragma unroll
        for (int s = 0; s < 32; s++) {
            int i = tid + s * 128;            // i = c*... -> d = i&63, c = i>>6
            int d = i & 63, c = i >> 6;
            float4 v = vw4[d * 64 + c];
            sw2[c * 64 + d] = *(ulonglong2*)&v;
        }
    }
    // stage t tile: coalesced reads, conflict-free writes
#pragma unroll
    for (int s = 0; s < (BT * 64) / 128; s++) {
        int i = tid + s * 128;
        int row = i >> 6, c = i & 63;
        t4[row * 64 + c] = ((const ulonglong2*)g_t)[((size_t)(b0 + row) * NH + h) * 64 + c];
    }
    if (tid < BT) coef_s[tid] = g_coef[(b0 + tid) * NH + h];
    __syncthreads();

    const int dq = tid & 15;    // d = dq + 16*di
    const int bq = tid >> 4;    // b = b0 + bq + 8*k

    unsigned long long accx[4][4], accy[4][4];
#pragma unroll
    for (int di = 0; di < 4; di++)
#pragma unroll
        for (int k = 0; k < 4; k++) { accx[di][k] = 0ull; accy[di][k] = 0ull; }

#pragma unroll 4
    for (int j4 = 0; j4 < 64; j4++) {
        ulonglong2 w[4], t[4];
#pragma unroll
        for (int di = 0; di < 4; di++) w[di] = sw2[j4 * 64 + dq + 16 * di];
#pragma unroll
        for (int k = 0; k < 4; k++)   t[k]  = t4[(bq + 8 * k) * 64 + j4];
#pragma unroll
        for (int di = 0; di < 4; di++)
#pragma unroll
            for (int k = 0; k < 4; k++) {
                accx[di][k] = f2fma(w[di].x, t[k].x, accx[di][k]);
                accy[di][k] = f2fma(w[di].y, t[k].y, accy[di][k]);
            }
    }

    float bv[4];
#pragma unroll
    for (int di = 0; di < 4; di++) bv[di] = vb[h * 64 + dq + 16 * di];

#pragma unroll
    for (int k = 0; k < 4; k++) {
        int bb = bq + 8 * k;
        float cf = coef_s[bb];
        float* op = out + (size_t)(b0 + bb) * DIMM + h * 64;
#pragma unroll
        for (int di = 0; di < 4; di++) {
            float r = (f2lo(accx[di][k]) + f2hi(accx[di][k]))
                    + (f2lo(accy[di][k]) + f2hi(accy[di][k]));
            op[dq + 16 * di] = fmaf(cf, bv[di], r);
        }
    }
}

// ---------------------------------------------------------------------------
extern "C" void kernel_launch(void* const* d_in, const int* in_sizes, int n_in,
                              void* d_out, int out_size) {
    const float* x     = (const float*)d_in[0];
    const int*   batch = (const int*)d_in[1];
    const float* q     = (const float*)d_in[2];
    const float* kw    = (const float*)d_in[3];
    const float* kb    = (const float*)d_in[4];
    const float* vw    = (const float*)d_in[5];
    const float* vb    = (const float*)d_in[6];
    float*       out   = (float*)d_out;

    const int smem_out = 64 * 64 * 16 + BT * 64 * 16 + BT * 4;   // 98432
    cudaFuncSetAttribute(k_out, cudaFuncAttributeMaxDynamicSharedMemorySize, smem_out);

    k_fold<<<NH, 256>>>(q, kw, kb);
    k_seg<<<NN / 256, 256>>>(batch);
    k_main<<<BSEG / 4, 128>>>(x);
    k_out<<<dim3(BSEG / BT, NH), 128, smem_out>>>(vw, vb, out);
}

// round 7
// speedup vs baseline: 1.5323x; 1.1661x over previous
#include <cuda_runtime.h>
#include <math.h>

#define NN   262144
#define DIMM 256
#define NH   4
#define HD   64
#define BSEG 4096
#define SCALE 0.125f
#define EPSV 1e-8f
#define BT   32     // b-tile per block in output kernel
#define RG   4      // k_main ring: group slots per warp (group = 2 rows)

// ---- device scratch ----
__device__ float g_wtil[NH * DIMM];
__device__ float g_ctil[NH];
__device__ int   g_segstart[BSEG + 1];
__device__ float g_t[BSEG * NH * DIMM];  // normalized weighted sums t~
__device__ float g_coef[BSEG * NH];      // esum/(esum+eps)

// ---- packed f32x2 helpers ----
__device__ __forceinline__ unsigned long long f2mul(unsigned long long a, unsigned long long b) {
    unsigned long long r; asm("mul.rn.f32x2 %0,%1,%2;" : "=l"(r) : "l"(a), "l"(b)); return r;
}
__device__ __forceinline__ unsigned long long f2fma(unsigned long long a, unsigned long long b,
                                                    unsigned long long c) {
    unsigned long long r; asm("fma.rn.f32x2 %0,%1,%2,%3;" : "=l"(r) : "l"(a), "l"(b), "l"(c)); return r;
}
__device__ __forceinline__ unsigned long long fpack(float a, float b) {
    unsigned long long r; asm("mov.b64 %0,{%1,%2};" : "=l"(r) : "f"(a), "f"(b)); return r;
}
__device__ __forceinline__ float f2lo(unsigned long long a) { float2 p = *(float2*)&a; return p.x; }
__device__ __forceinline__ float f2hi(unsigned long long a) { float2 p = *(float2*)&a; return p.y; }

__device__ __forceinline__ void cpa16(void* dst_smem, const void* src) {
    unsigned u = (unsigned)__cvta_generic_to_shared(dst_smem);
    asm volatile("cp.async.cg.shared.global [%0], [%1], 16;" :: "r"(u), "l"(src) : "memory");
}
#define CP_COMMIT() asm volatile("cp.async.commit_group;" ::: "memory")
#define CP_WAIT(n)  asm volatile("cp.async.wait_group %0;" :: "n"(n) : "memory")

// ---------------------------------------------------------------------------
__global__ void k_fold(const float* __restrict__ q,
                       const float* __restrict__ kw,
                       const float* __restrict__ kb) {
    int h = blockIdx.x;
    int j = threadIdx.x;
    float acc = 0.f;
#pragma unroll 8
    for (int d = 0; d < HD; d++)
        acc = fmaf(q[h * HD + d], kw[(h * HD + d) * DIMM + j], acc);
    g_wtil[h * DIMM + j] = acc * SCALE;
    if (j == 0) {
        float c = 0.f;
#pragma unroll 8
        for (int d = 0; d < HD; d++)
            c = fmaf(q[h * HD + d], kb[h * HD + d], c);
        g_ctil[h] = c * SCALE;
    }
}

// ---------------------------------------------------------------------------
__global__ void k_seg(const int* __restrict__ batch) {
    int i = blockIdx.x * blockDim.x + threadIdx.x;
    if (i >= NN) return;
    int cur  = batch[i];
    int prev = (i == 0) ? -1 : batch[i - 1];
    for (int b = prev + 1; b <= cur; b++) g_segstart[b] = i;
    if (i == NN - 1)
        for (int b = cur + 1; b <= BSEG; b++) g_segstart[b] = NN;
}

// ---------------------------------------------------------------------------
// 2-row compute: 8-item butterfly multi-reduce -> exp -> broadcast -> f32x2
// register accumulation. Item = r_local*4 + h; lane (lane>>2)&7 owns item.
// ---------------------------------------------------------------------------
__device__ __forceinline__ void process_pair(
    ulonglong2 v0, ulonglong2 v1, ulonglong2 u0, ulonglong2 u1,
    bool row1ok, int lane, float ctv,
    const ulonglong2 (&w0)[NH], const ulonglong2 (&w1)[NH],
    ulonglong2 (&accA)[NH], ulonglong2 (&accB)[NH], float& es)
{
    float a[8];
#pragma unroll
    for (int h = 0; h < NH; h++) {
        unsigned long long p;
        p = f2mul(v0.x, w0[h].x); p = f2fma(v0.y, w0[h].y, p);
        p = f2fma(v1.x, w1[h].x, p); p = f2fma(v1.y, w1[h].y, p);
        a[h] = f2lo(p) + f2hi(p);
        p = f2mul(u0.x, w0[h].x); p = f2fma(u0.y, w0[h].y, p);
        p = f2fma(u1.x, w1[h].x, p); p = f2fma(u1.y, w1[h].y, p);
        a[4 + h] = f2lo(p) + f2hi(p);
    }
    const bool b4 = (lane & 16) != 0;
#pragma unroll
    for (int i = 0; i < 4; i++) {
        float mine = b4 ? a[i + 4] : a[i];
        float oth  = b4 ? a[i]     : a[i + 4];
        oth = __shfl_xor_sync(0xffffffffu, oth, 16);
        a[i] = mine + oth;
    }
    const bool b3 = (lane & 8) != 0;
#pragma unroll
    for (int i = 0; i < 2; i++) {
        float mine = b3 ? a[i + 2] : a[i];
        float oth  = b3 ? a[i]     : a[i + 2];
        oth = __shfl_xor_sync(0xffffffffu, oth, 8);
        a[i] = mine + oth;
    }
    const bool b2 = (lane & 4) != 0;
    float mine = b2 ? a[1] : a[0];
    float oth  = b2 ? a[0] : a[1];
    oth = __shfl_xor_sync(0xffffffffu, oth, 4);
    float c = mine + oth;
    c += __shfl_xor_sync(0xffffffffu, c, 2);
    c += __shfl_xor_sync(0xffffffffu, c, 1);

    float e = __expf(c + ctv);
    if (lane >= 16 && !row1ok) e = 0.f;
    if ((lane & 3) == 0) es += e;

    float e00 = __shfl_sync(0xffffffffu, e, 0);
    float e01 = __shfl_sync(0xffffffffu, e, 4);
    float e02 = __shfl_sync(0xffffffffu, e, 8);
    float e03 = __shfl_sync(0xffffffffu, e, 12);
    float e10 = __shfl_sync(0xffffffffu, e, 16);
    float e11 = __shfl_sync(0xffffffffu, e, 20);
    float e12 = __shfl_sync(0xffffffffu, e, 24);
    float e13 = __shfl_sync(0xffffffffu, e, 28);

    unsigned long long k0 = fpack(e00, e00), k1 = fpack(e01, e01);
    unsigned long long k2 = fpack(e02, e02), k3 = fpack(e03, e03);
    unsigned long long m0 = fpack(e10, e10), m1 = fpack(e11, e11);
    unsigned long long m2 = fpack(e12, e12), m3 = fpack(e13, e13);

    accA[0].x = f2fma(k0, v0.x, accA[0].x); accA[0].y = f2fma(k0, v0.y, accA[0].y);
    accB[0].x = f2fma(k0, v1.x, accB[0].x); accB[0].y = f2fma(k0, v1.y, accB[0].y);
    accA[1].x = f2fma(k1, v0.x, accA[1].x); accA[1].y = f2fma(k1, v0.y, accA[1].y);
    accB[1].x = f2fma(k1, v1.x, accB[1].x); accB[1].y = f2fma(k1, v1.y, accB[1].y);
    accA[2].x = f2fma(k2, v0.x, accA[2].x); accA[2].y = f2fma(k2, v0.y, accA[2].y);
    accB[2].x = f2fma(k2, v1.x, accB[2].x); accB[2].y = f2fma(k2, v1.y, accB[2].y);
    accA[3].x = f2fma(k3, v0.x, accA[3].x); accA[3].y = f2fma(k3, v0.y, accA[3].y);
    accB[3].x = f2fma(k3, v1.x, accB[3].x); accB[3].y = f2fma(k3, v1.y, accB[3].y);

    accA[0].x = f2fma(m0, u0.x, accA[0].x); accA[0].y = f2fma(m0, u0.y, accA[0].y);
    accB[0].x = f2fma(m0, u1.x, accB[0].x); accB[0].y = f2fma(m0, u1.y, accB[0].y);
    accA[1].x = f2fma(m1, u0.x, accA[1].x); accA[1].y = f2fma(m1, u0.y, accA[1].y);
    accB[1].x = f2fma(m1, u1.x, accB[1].x); accB[1].y = f2fma(m1, u1.y, accB[1].y);
    accA[2].x = f2fma(m2, u0.x, accA[2].x); accA[2].y = f2fma(m2, u0.y, accA[2].y);
    accB[2].x = f2fma(m2, u1.x, accB[2].x); accB[2].y = f2fma(m2, u1.y, accB[2].y);
    accA[3].x = f2fma(m3, u0.x, accA[3].x); accA[3].y = f2fma(m3, u0.y, accA[3].y);
    accB[3].x = f2fma(m3, u1.x, accB[3].x); accB[3].y = f2fma(m3, u1.y, accB[3].y);
}

// ---------------------------------------------------------------------------
// k_main: warp per segment, cp.async smem ring (4 slots x 2 rows, prefetch 3
// groups ahead = 6KB in flight per warp). Each lane copies and reads back ITS
// OWN 16B chunks -> no barriers needed, wait_group is per-thread.
// dyn smem: 8 warps * RG * 128 float4 = 64KB.
// ---------------------------------------------------------------------------
__global__ void __launch_bounds__(256) k_main(const float* __restrict__ x) {
    extern __shared__ float4 ring_all[];
    const int lane = threadIdx.x & 31;
    const int wid  = threadIdx.x >> 5;
    const int b    = blockIdx.x * 8 + wid;
    float4* ring = ring_all + wid * (RG * 128);

    const int s0  = g_segstart[b];
    const int s1  = g_segstart[b + 1];
    const int cnt = s1 - s0;
    const int ng  = (cnt + 1) >> 1;

    const float4* wt4 = (const float4*)g_wtil;
    ulonglong2 w0[NH], w1[NH];
#pragma unroll
    for (int h = 0; h < NH; h++) {
        float4 t = wt4[h * 64 + lane];      w0[h] = *(ulonglong2*)&t;
        float4 u = wt4[h * 64 + 32 + lane]; w1[h] = *(ulonglong2*)&u;
    }
    const float ctv = g_ctil[(lane >> 2) & 3];

    ulonglong2 accA[NH], accB[NH];
#pragma unroll
    for (int h = 0; h < NH; h++) { accA[h].x = accA[h].y = 0ull; accB[h].x = accB[h].y = 0ull; }
    float es = 0.f;

    const float4* xp = (const float4*)x;

#define ISSUE(G) do {                                             \
        int slot_ = (G) & (RG - 1);                               \
        int r0_ = s0 + 2 * (G);                                   \
        int r1_ = (2 * (G) + 1 < cnt) ? r0_ + 1 : r0_;            \
        float4* d_ = ring + slot_ * 128;                          \
        cpa16(d_ + lane,      xp + (size_t)r0_ * 64 + lane);      \
        cpa16(d_ + 32 + lane, xp + (size_t)r0_ * 64 + 32 + lane); \
        cpa16(d_ + 64 + lane, xp + (size_t)r1_ * 64 + lane);      \
        cpa16(d_ + 96 + lane, xp + (size_t)r1_ * 64 + 32 + lane); \
    } while (0)

#pragma unroll
    for (int p = 0; p < 3; p++) { if (p < ng) ISSUE(p); CP_COMMIT(); }

    for (int g = 0; g < ng; g++) {
        if (g + 3 < ng) ISSUE(g + 3);
        CP_COMMIT();          // one commit per iteration keeps group math uniform
        CP_WAIT(3);           // <=3 pending -> group g complete (for this lane)
        const float4* sl = ring + (g & (RG - 1)) * 128;
        float4 f0 = sl[lane], f1 = sl[32 + lane];
        float4 f2v = sl[64 + lane], f3 = sl[96 + lane];
        process_pair(*(ulonglong2*)&f0, *(ulonglong2*)&f1,
                     *(ulonglong2*)&f2v, *(ulonglong2*)&f3,
                     (2 * g + 1) < cnt, lane, ctv, w0, w1, accA, accB, es);
    }
#undef ISSUE

    es += __shfl_xor_sync(0xffffffffu, es, 16);
    float es0 = __shfl_sync(0xffffffffu, es, 0);
    float es1 = __shfl_sync(0xffffffffu, es, 4);
    float es2 = __shfl_sync(0xffffffffu, es, 8);
    float es3 = __shfl_sync(0xffffffffu, es, 12);

    float iv0 = 1.0f / (es0 + EPSV), iv1 = 1.0f / (es1 + EPSV);
    float iv2 = 1.0f / (es2 + EPSV), iv3 = 1.0f / (es3 + EPSV);
    unsigned long long ii[NH] = { fpack(iv0, iv0), fpack(iv1, iv1),
                                  fpack(iv2, iv2), fpack(iv3, iv3) };
    float4* tp = (float4*)(g_t + (size_t)b * NH * DIMM);
#pragma unroll
    for (int h = 0; h < NH; h++) {
        ulonglong2 sa, sb;
        sa.x = f2mul(ii[h], accA[h].x); sa.y = f2mul(ii[h], accA[h].y);
        sb.x = f2mul(ii[h], accB[h].x); sb.y = f2mul(ii[h], accB[h].y);
        tp[h * 64 + lane]      = *(float4*)&sa;
        tp[h * 64 + 32 + lane] = *(float4*)&sb;
    }
    if (lane < NH) {
        float cf = (lane == 0) ? es0 * iv0 : (lane == 1) ? es1 * iv1
                 : (lane == 2) ? es2 * iv2 : es3 * iv3;
        g_coef[b * NH + lane] = cf;
    }
}

// ---------------------------------------------------------------------------
// k_out: 256 threads, 4d x 2b register tile, f32x2. w transposed [j4][d] with
// row stride 65 f4 (pad) -> conflict-free STS on staging AND LDS in loop;
// t tile padded to stride 65 -> the two per-warp broadcasts hit disjoint banks.
// Staging reads are fully coalesced.  grid = (BSEG/BT, NH).
// ---------------------------------------------------------------------------
__global__ void __launch_bounds__(256) k_out(const float* __restrict__ vw,
                                             const float* __restrict__ vb,
                                             float* __restrict__ out) {
    extern __shared__ float sm[];
    ulonglong2* sw2    = (ulonglong2*)sm;                      // [j4][d] stride 65
    ulonglong2* t4     = (ulonglong2*)(sm + 64 * 65 * 4);      // [b][j4] stride 65
    float*      coef_s = sm + 64 * 65 * 4 + BT * 65 * 4;

    const int h   = blockIdx.y;
    const int b0  = blockIdx.x * BT;
    const int tid = threadIdx.x;

    // stage w: coalesced global reads, transposed padded smem writes
    {
        const float4* vw4 = (const float4*)(vw + (size_t)h * 64 * DIMM);
#pragma unroll
        for (int s = 0; s < 16; s++) {
            int i = tid + s * 256;             // d = i>>6, c = i&63
            int d = i >> 6, c = i & 63;
            float4 v = vw4[i];
            sw2[c * 65 + d] = *(ulonglong2*)&v;   // stride 65 -> conflict-free
        }
    }
    // stage t tile: coalesced reads, padded writes
#pragma unroll
    for (int s = 0; s < (BT * 64) / 256; s++) {
        int i = tid + s * 256;
        int row = i >> 6, c = i & 63;
        t4[row * 65 + c] = ((const ulonglong2*)g_t)[((size_t)(b0 + row) * NH + h) * 64 + c];
    }
    if (tid < BT) coef_s[tid] = g_coef[(b0 + tid) * NH + h];
    __syncthreads();

    const int dq = tid & 15;    // d = dq + 16*di, di=0..3
    const int bq = tid >> 4;    // b = b0 + bq + 16*k, k=0..1

    unsigned long long accx[4][2], accy[4][2];
#pragma unroll
    for (int di = 0; di < 4; di++)
#pragma unroll
        for (int k = 0; k < 2; k++) { accx[di][k] = 0ull; accy[di][k] = 0ull; }

#pragma unroll 4
    for (int j4 = 0; j4 < 64; j4++) {
        ulonglong2 w[4], t[2];
#pragma unroll
        for (int di = 0; di < 4; di++) w[di] = sw2[j4 * 65 + dq + 16 * di];
#pragma unroll
        for (int k = 0; k < 2; k++)   t[k]  = t4[(bq + 16 * k) * 65 + j4];
#pragma unroll
        for (int di = 0; di < 4; di++)
#pragma unroll
            for (int k = 0; k < 2; k++) {
                accx[di][k] = f2fma(w[di].x, t[k].x, accx[di][k]);
                accy[di][k] = f2fma(w[di].y, t[k].y, accy[di][k]);
            }
    }

    float bv[4];
#pragma unroll
    for (int di = 0; di < 4; di++) bv[di] = vb[h * 64 + dq + 16 * di];

#pragma unroll
    for (int k = 0; k < 2; k++) {
        int bb = bq + 16 * k;
        float cf = coef_s[bb];
        float* op = out + (size_t)(b0 + bb) * DIMM + h * 64;
#pragma unroll
        for (int di = 0; di < 4; di++) {
            float r = (f2lo(accx[di][k]) + f2hi(accx[di][k]))
                    + (f2lo(accy[di][k]) + f2hi(accy[di][k]));
            op[dq + 16 * di] = fmaf(cf, bv[di], r);
        }
    }
}

// ---------------------------------------------------------------------------
extern "C" void kernel_launch(void* const* d_in, const int* in_sizes, int n_in,
                              void* d_out, int out_size) {
    const float* x     = (const float*)d_in[0];
    const int*   batch = (const int*)d_in[1];
    const float* q     = (const float*)d_in[2];
    const float* kw    = (const float*)d_in[3];
    const float* kb    = (const float*)d_in[4];
    const float* vw    = (const float*)d_in[5];
    const float* vb    = (const float*)d_in[6];
    float*       out   = (float*)d_out;

    const int smem_main = 8 * RG * 128 * 16;                       // 65536
    const int smem_out  = 64 * 65 * 16 + BT * 65 * 16 + BT * 4;    // 99968
    cudaFuncSetAttribute(k_main, cudaFuncAttributeMaxDynamicSharedMemorySize, smem_main);
    cudaFuncSetAttribute(k_out,  cudaFuncAttributeMaxDynamicSharedMemorySize, smem_out);

    k_fold<<<NH, 256>>>(q, kw, kb);
    k_seg<<<NN / 256, 256>>>(batch);
    k_main<<<BSEG / 8, 256, smem_main>>>(x);
    k_out<<<dim3(BSEG / BT, NH), 256, smem_out>>>(vw, vb, out);
}